// round 1
// baseline (speedup 1.0000x reference)
#include <cuda_runtime.h>

#define HD 256
#define NMAX 50048
#define EMAX 800000
#define NGR 64

// ---------------- device scratch (static, no runtime alloc) ----------------
__device__ float g_agg [(size_t)NMAX * HD];
__device__ float g_hbuf[(size_t)NMAX * HD];
__device__ float g_xa  [(size_t)NMAX * HD];
__device__ float g_xb  [(size_t)NMAX * HD];
__device__ int   g_src [EMAX];
__device__ int   g_dstv[EMAX];
__device__ int   g_nbr [EMAX];
__device__ int   g_deg [NMAX];
__device__ int   g_off [NMAX + 1];
__device__ int   g_cur [NMAX];
__device__ int   g_batch[NMAX];
__device__ float g_colsum[HD];
__device__ float g_colsq [HD];
__device__ float g_pool[NGR * HD];
__device__ float g_cnt [NGR];
__device__ int   g_flags[2];   // [0]=edge_index is int64, [1]=batch is int64

// ---------------- dtype sniffing + index normalization ----------------
__global__ void k_detect(const int* __restrict__ ei, const int* __restrict__ bat, int N)
{
    if (threadIdx.x == 0 && blockIdx.x == 0) {
        // int64 little-endian: odd int32 words of first elements are hi-words == 0
        int e64 = (ei[1] == 0 && ei[3] == 0 && ei[5] == 0 && ei[7] == 0) ? 1 : 0;
        // batch is sorted 0..63; pick an odd word index near the end.
        // int64 -> hi word == 0 ; int32 -> last graph id (>0 w.h.p.)
        int w = N - 1; if (!(w & 1)) w--;
        int b64 = (bat[w] == 0) ? 1 : 0;
        g_flags[0] = e64;
        g_flags[1] = b64;
    }
}

__global__ void k_convert(const int* __restrict__ ei, const int* __restrict__ bat, int E, int N)
{
    int i = blockIdx.x * blockDim.x + threadIdx.x;
    int e64 = g_flags[0], b64 = g_flags[1];
    if (i < E) {
        if (e64) { g_src[i] = ei[2 * i]; g_dstv[i] = ei[2 * (E + i)]; }
        else     { g_src[i] = ei[i];     g_dstv[i] = ei[E + i]; }
    }
    if (i < N) {
        g_batch[i] = b64 ? bat[2 * i] : bat[i];
    }
}

// ---------------- CSR build (by dst) ----------------
__global__ void k_count(int E)
{
    int i = blockIdx.x * blockDim.x + threadIdx.x;
    if (i < E) atomicAdd(&g_deg[g_dstv[i]], 1);
}

__global__ void k_scan(int N)
{
    __shared__ int sm[1024];
    __shared__ int carry;
    int t = threadIdx.x;
    if (t == 0) { carry = 0; g_off[0] = 0; }
    __syncthreads();
    for (int base = 0; base < N; base += 1024) {
        int i = base + t;
        int v = (i < N) ? g_deg[i] : 0;
        sm[t] = v;
        __syncthreads();
        for (int off = 1; off < 1024; off <<= 1) {
            int add = (t >= off) ? sm[t - off] : 0;
            __syncthreads();
            sm[t] += add;
            __syncthreads();
        }
        int res = carry + sm[t];
        if (i < N) g_off[i + 1] = res;
        __syncthreads();
        if (t == 1023) carry += sm[1023];
        __syncthreads();
    }
}

__global__ void k_copycur(int N)
{
    int i = blockIdx.x * blockDim.x + threadIdx.x;
    if (i < N) g_cur[i] = g_off[i];
}

__global__ void k_fill(int E)
{
    int i = blockIdx.x * blockDim.x + threadIdx.x;
    if (i < E) {
        int d = g_dstv[i];
        int p = atomicAdd(&g_cur[d], 1);
        g_nbr[p] = g_src[i];
    }
}

// ---------------- GIN aggregation: out[i] = x[i] + sum_{j in N(i)} x[j] ----------------
__global__ void k_gather128(const float* __restrict__ xin, float* __restrict__ out, int N)
{
    int gt = blockIdx.x * blockDim.x + threadIdx.x;
    int w = gt >> 5, lane = gt & 31;
    if (w >= N) return;
    const float4* xp = (const float4*)xin;
    float4 a = xp[(size_t)w * 32 + lane];
    int e1 = g_off[w + 1];
    for (int e = g_off[w]; e < e1; e++) {
        int nb = g_nbr[e];
        float4 v = xp[(size_t)nb * 32 + lane];
        a.x += v.x; a.y += v.y; a.z += v.z; a.w += v.w;
    }
    ((float4*)out)[(size_t)w * 32 + lane] = a;
}

__global__ void k_gather256(const float* __restrict__ xin, float* __restrict__ out, int N)
{
    int gt = blockIdx.x * blockDim.x + threadIdx.x;
    int w = gt >> 5, lane = gt & 31;
    if (w >= N) return;
    const float4* xp = (const float4*)xin;
    float4 a0 = xp[(size_t)w * 64 + lane];
    float4 a1 = xp[(size_t)w * 64 + 32 + lane];
    int e1 = g_off[w + 1];
    for (int e = g_off[w]; e < e1; e++) {
        size_t b = (size_t)g_nbr[e] * 64;
        float4 v0 = xp[b + lane];
        float4 v1 = xp[b + 32 + lane];
        a0.x += v0.x; a0.y += v0.y; a0.z += v0.z; a0.w += v0.w;
        a1.x += v1.x; a1.y += v1.y; a1.z += v1.z; a1.w += v1.w;
    }
    ((float4*)out)[(size_t)w * 64 + lane]      = a0;
    ((float4*)out)[(size_t)w * 64 + 32 + lane] = a1;
}

// ---------------- GEMM: H = A[M,K] @ W[K,256] + b, with fused column sum/sumsq ----------------
template <int K>
__launch_bounds__(256, 2)
__global__ void k_gemm(const float* __restrict__ A, const float* __restrict__ W,
                       const float* __restrict__ bias, float* __restrict__ Hout, int M)
{
    const int BM = 128, BN = 128, BK = 16;
    __shared__ float As[BK][132];   // padded vs 128 to dodge store conflicts, keeps 16B align
    __shared__ float Bs[BK][BN];
    __shared__ float Red[16][BN];
    int bm = blockIdx.x * BM, bn = blockIdx.y * BN;
    int t = threadIdx.x;
    int tx = t & 15, ty = t >> 4;

    float acc[8][8];
#pragma unroll
    for (int i = 0; i < 8; i++)
#pragma unroll
        for (int j = 0; j < 8; j++) acc[i][j] = 0.f;

    for (int k0 = 0; k0 < K; k0 += BK) {
#pragma unroll
        for (int s = 0; s < 2; s++) {
            int f = t + s * 256;
            int row = f >> 2;
            int c4 = f & 3;
            int gr = bm + row;
            float4 v = make_float4(0.f, 0.f, 0.f, 0.f);
            if (gr < M) v = *(const float4*)(A + (size_t)gr * K + k0 + c4 * 4);
            As[c4 * 4 + 0][row] = v.x;
            As[c4 * 4 + 1][row] = v.y;
            As[c4 * 4 + 2][row] = v.z;
            As[c4 * 4 + 3][row] = v.w;
        }
#pragma unroll
        for (int s = 0; s < 2; s++) {
            int f = t + s * 256;
            int row = f >> 5;
            int c4 = f & 31;
            *(float4*)&Bs[row][c4 * 4] = *(const float4*)(W + (size_t)(k0 + row) * HD + bn + c4 * 4);
        }
        __syncthreads();
#pragma unroll
        for (int kk = 0; kk < BK; kk++) {
            float ra[8], rb[8];
            *(float4*)&ra[0] = *(const float4*)&As[kk][ty * 8];
            *(float4*)&ra[4] = *(const float4*)&As[kk][ty * 8 + 4];
            *(float4*)&rb[0] = *(const float4*)&Bs[kk][tx * 8];
            *(float4*)&rb[4] = *(const float4*)&Bs[kk][tx * 8 + 4];
#pragma unroll
            for (int i = 0; i < 8; i++)
#pragma unroll
                for (int j = 0; j < 8; j++)
                    acc[i][j] = fmaf(ra[i], rb[j], acc[i][j]);
        }
        __syncthreads();
    }

    // epilogue: bias, store, per-column sum/sumsq for BN
    float bv[8], cs[8], cq[8];
#pragma unroll
    for (int j = 0; j < 8; j++) { bv[j] = bias[bn + tx * 8 + j]; cs[j] = 0.f; cq[j] = 0.f; }
#pragma unroll
    for (int i = 0; i < 8; i++) {
        int gr = bm + ty * 8 + i;
        if (gr < M) {
            float o[8];
#pragma unroll
            for (int j = 0; j < 8; j++) {
                float v = acc[i][j] + bv[j];
                o[j] = v; cs[j] += v; cq[j] += v * v;
            }
            float* dst = Hout + (size_t)gr * HD + bn + tx * 8;
            *(float4*)dst       = make_float4(o[0], o[1], o[2], o[3]);
            *(float4*)(dst + 4) = make_float4(o[4], o[5], o[6], o[7]);
        }
    }
#pragma unroll
    for (int j = 0; j < 8; j++) Red[ty][tx * 8 + j] = cs[j];
    __syncthreads();
    if (t < BN) {
        float s = 0.f;
#pragma unroll
        for (int r = 0; r < 16; r++) s += Red[r][t];
        atomicAdd(&g_colsum[bn + t], s);
    }
    __syncthreads();
#pragma unroll
    for (int j = 0; j < 8; j++) Red[ty][tx * 8 + j] = cq[j];
    __syncthreads();
    if (t < BN) {
        float s = 0.f;
#pragma unroll
        for (int r = 0; r < 16; r++) s += Red[r][t];
        atomicAdd(&g_colsq[bn + t], s);
    }
}

// ---------------- BN (train-mode, biased var) + ReLU (+ residual) ----------------
__global__ void k_bnrelu(const float* __restrict__ Hin, const float* __restrict__ gam,
                         const float* __restrict__ bet, const float* __restrict__ resid,
                         float* __restrict__ out, int M)
{
    size_t idx = (size_t)blockIdx.x * blockDim.x + threadIdx.x;
    size_t tot = (size_t)M * (HD / 4);
    if (idx >= tot) return;
    int c4 = (int)(idx & 63);   // HD/4 == 64
    float invN = 1.0f / (float)M;
    float4 h = ((const float4*)Hin)[idx];
    float hv[4] = { h.x, h.y, h.z, h.w };
    float o[4];
#pragma unroll
    for (int j = 0; j < 4; j++) {
        int c = c4 * 4 + j;
        float m = g_colsum[c] * invN;
        float v = fmaf(-m, m, g_colsq[c] * invN);
        float sc = gam[c] * rsqrtf(v + 1e-5f);
        float sh = fmaf(-m, sc, bet[c]);
        o[j] = fmaxf(fmaf(hv[j], sc, sh), 0.0f);
    }
    if (resid) {
        float4 rr = ((const float4*)resid)[idx];
        o[0] += rr.x; o[1] += rr.y; o[2] += rr.z; o[3] += rr.w;
    }
    ((float4*)out)[idx] = make_float4(o[0], o[1], o[2], o[3]);
}

// ---------------- global mean pool (segment sum + counts) ----------------
__global__ void k_pool(const float* __restrict__ x3, int N)
{
    int gt = blockIdx.x * blockDim.x + threadIdx.x;
    int w = gt >> 5, lane = gt & 31;
    if (w >= N) return;
    int g = g_batch[w];
    const float4* xp = (const float4*)(x3 + (size_t)w * HD);
    float* pp = g_pool + g * HD;
#pragma unroll
    for (int c = 0; c < 2; c++) {
        float4 v = xp[lane + c * 32];
        int col = (lane + c * 32) * 4;
        atomicAdd(pp + col + 0, v.x);
        atomicAdd(pp + col + 1, v.y);
        atomicAdd(pp + col + 2, v.z);
        atomicAdd(pp + col + 3, v.w);
    }
    if (lane == 0) atomicAdd(&g_cnt[g], 1.0f);
}

// ---------------- final MLP head (64 graphs) ----------------
__global__ void k_final(const float* __restrict__ fcW1, const float* __restrict__ fcb1,
                        const float* __restrict__ fcW2, const float* __restrict__ fcb2,
                        float* __restrict__ out)
{
    __shared__ float prow[HD];
    __shared__ float hred[HD];
    int g = blockIdx.x, t = threadIdx.x;
    float cnt = fmaxf(g_cnt[g], 1.0f);
    prow[t] = g_pool[g * HD + t] / cnt;
    __syncthreads();
    float acc = fcb1[t];
    for (int k = 0; k < HD; k++)
        acc = fmaf(prow[k], __ldg(fcW1 + (size_t)k * HD + t), acc);
    float h = fmaxf(acc, 0.0f);
    hred[t] = h * fcW2[t];
    __syncthreads();
    for (int s = HD / 2; s > 0; s >>= 1) {
        if (t < s) hred[t] += hred[t + s];
        __syncthreads();
    }
    if (t == 0) out[g] = hred[0] + fcb2[0];
}

// ---------------- launch ----------------
extern "C" void kernel_launch(void* const* d_in, const int* in_sizes, int n_in,
                              void* d_out, int out_size)
{
    // inputs: x, edge_index, batch, [num_graphs], W1,b1,W2,b2,W3,b3,
    //         g1,be1,g2,be2,g3,be3, fcW1,fcb1,fcW2,fcb2
    int base = 3;
    if (n_in >= 20 && in_sizes[3] == 1) base = 4;

    const float* x   = (const float*)d_in[0];
    const int*   ei  = (const int*)d_in[1];
    const int*   bat = (const int*)d_in[2];
    const float* W1  = (const float*)d_in[base + 0];
    const float* b1  = (const float*)d_in[base + 1];
    const float* W2  = (const float*)d_in[base + 2];
    const float* b2  = (const float*)d_in[base + 3];
    const float* W3  = (const float*)d_in[base + 4];
    const float* b3  = (const float*)d_in[base + 5];
    const float* ga1 = (const float*)d_in[base + 6];
    const float* be1 = (const float*)d_in[base + 7];
    const float* ga2 = (const float*)d_in[base + 8];
    const float* be2 = (const float*)d_in[base + 9];
    const float* ga3 = (const float*)d_in[base + 10];
    const float* be3 = (const float*)d_in[base + 11];
    const float* fcW1 = (const float*)d_in[base + 12];
    const float* fcb1 = (const float*)d_in[base + 13];
    const float* fcW2 = (const float*)d_in[base + 14];
    const float* fcb2 = (const float*)d_in[base + 15];

    int N = in_sizes[0] / 128;
    int E = in_sizes[1] / 2;

    void* p;
    float *agg, *hbuf, *xa, *xb;
    cudaGetSymbolAddress(&p, g_agg);  agg  = (float*)p;
    cudaGetSymbolAddress(&p, g_hbuf); hbuf = (float*)p;
    cudaGetSymbolAddress(&p, g_xa);   xa   = (float*)p;
    cudaGetSymbolAddress(&p, g_xb);   xb   = (float*)p;
    void *pdeg, *pcs, *pcq, *ppool, *pcnt;
    cudaGetSymbolAddress(&pdeg, g_deg);
    cudaGetSymbolAddress(&pcs,  g_colsum);
    cudaGetSymbolAddress(&pcq,  g_colsq);
    cudaGetSymbolAddress(&ppool, g_pool);
    cudaGetSymbolAddress(&pcnt,  g_cnt);

    const int tb = 256;
    int ebl = (E + tb - 1) / tb;
    int nbl = (N + tb - 1) / tb;
    int wbl = (N * 32 + tb - 1) / tb;
    int bnbl = (int)(((size_t)N * (HD / 4) + tb - 1) / tb);
    dim3 ggrid((N + 127) / 128, 2);

    // index normalization + CSR (shared by all 3 layers)
    k_detect<<<1, 32>>>(ei, bat, N);
    k_convert<<<ebl, tb>>>(ei, bat, E, N);
    cudaMemsetAsync(pdeg, 0, (size_t)N * sizeof(int));
    k_count<<<ebl, tb>>>(E);
    k_scan<<<1, 1024>>>(N);
    k_copycur<<<nbl, tb>>>(N);
    k_fill<<<ebl, tb>>>(E);

    // layer 1: D=128
    k_gather128<<<wbl, tb>>>(x, agg, N);
    cudaMemsetAsync(pcs, 0, HD * sizeof(float));
    cudaMemsetAsync(pcq, 0, HD * sizeof(float));
    k_gemm<128><<<ggrid, 256>>>(agg, W1, b1, hbuf, N);
    k_bnrelu<<<bnbl, tb>>>(hbuf, ga1, be1, nullptr, xa, N);

    // layer 2
    k_gather256<<<wbl, tb>>>(xa, agg, N);
    cudaMemsetAsync(pcs, 0, HD * sizeof(float));
    cudaMemsetAsync(pcq, 0, HD * sizeof(float));
    k_gemm<256><<<ggrid, 256>>>(agg, W2, b2, hbuf, N);
    k_bnrelu<<<bnbl, tb>>>(hbuf, ga2, be2, xa, xb, N);

    // layer 3
    k_gather256<<<wbl, tb>>>(xb, agg, N);
    cudaMemsetAsync(pcs, 0, HD * sizeof(float));
    cudaMemsetAsync(pcq, 0, HD * sizeof(float));
    k_gemm<256><<<ggrid, 256>>>(agg, W3, b3, hbuf, N);
    k_bnrelu<<<bnbl, tb>>>(hbuf, ga3, be3, xb, xa, N);

    // pool + head
    cudaMemsetAsync(ppool, 0, NGR * HD * sizeof(float));
    cudaMemsetAsync(pcnt, 0, NGR * sizeof(float));
    k_pool<<<wbl, tb>>>(xa, N);
    k_final<<<NGR, 256>>>(fcW1, fcb1, fcW2, fcb2, (float*)d_out);
}